// round 2
// baseline (speedup 1.0000x reference)
#include <cuda_runtime.h>

// Problem shape (fixed by the dataset)
#define BB 16
#define NN 2048
#define DD 768
#define ROWS (BB * NN)   // 32768

// Scratch (allocation-free rule: __device__ globals)
__device__ float g_invq[ROWS];
__device__ float g_invc[ROWS];
__device__ float g_maxs[ROWS];
__device__ int   g_maxi[ROWS];

// ---------------------------------------------------------------------------
// Kernel A: inverse L2 norms, one warp per row, for both Q-input and C-input.
// ---------------------------------------------------------------------------
__global__ void invnorm_kernel(const float* __restrict__ Q,
                               const float* __restrict__ C) {
    int gwarp = (blockIdx.x * blockDim.x + threadIdx.x) >> 5;
    int lane  = threadIdx.x & 31;
    if (gwarp >= 2 * ROWS) return;
    bool isQ = gwarp < ROWS;
    int row  = isQ ? gwarp : (gwarp - ROWS);
    const float4* p = (const float4*)((isQ ? Q : C) + (size_t)row * DD);
    float s = 0.f;
#pragma unroll
    for (int i = 0; i < DD / 4 / 32; i++) {   // 6 float4 per lane
        float4 v = p[lane + 32 * i];
        s += v.x * v.x + v.y * v.y + v.z * v.z + v.w * v.w;
    }
#pragma unroll
    for (int o = 16; o > 0; o >>= 1) s += __shfl_xor_sync(0xffffffffu, s, o);
    if (lane == 0) {
        float inv = rsqrtf(s);
        if (isQ) g_invq[row] = inv; else g_invc[row] = inv;
    }
}

// ---------------------------------------------------------------------------
// Kernel B: streaming SGEMM-argmax.
// Block = 64 query rows of one batch. Iterates all 2048 cached rows in 64-col
// tiles, 16-wide K tiles, 4x4 register micro-tile per thread (16x16 threads).
// Running (max,argmax) kept in registers; invc applied at compare time,
// invq applied once at the end (positive scale -> argmax-invariant).
// ---------------------------------------------------------------------------
__global__ __launch_bounds__(256) void simargmax_kernel(
    const float* __restrict__ Q, const float* __restrict__ C) {
    __shared__ float As[16][64];
    __shared__ float Bs[16][64];
    __shared__ float sInvC[64];
    __shared__ float sV[256];
    __shared__ int   sI[256];

    const int b    = blockIdx.y;
    const int row0 = blockIdx.x * 64;
    const int tid  = threadIdx.x;
    const int tx   = tid & 15;
    const int ty   = tid >> 4;
    const float* Qb = Q + (size_t)b * NN * DD;
    const float* Cb = C + (size_t)b * NN * DD;

    // tile-load mapping: 256 threads load 64 rows x 16 k (as float4)
    const int lm  = tid >> 2;        // 0..63 (row within tile)
    const int lk4 = (tid & 3) * 4;   // 0,4,8,12 (k offset)

    float best[4];
    int   bidx[4];
#pragma unroll
    for (int i = 0; i < 4; i++) { best[i] = -1e30f; bidx[i] = 0; }

    for (int mt = 0; mt < NN / 64; mt++) {
        const int col0 = mt * 64;
        float acc[4][4];
#pragma unroll
        for (int i = 0; i < 4; i++)
#pragma unroll
            for (int j = 0; j < 4; j++) acc[i][j] = 0.f;

        for (int kt = 0; kt < DD / 16; kt++) {
            __syncthreads();   // protect prior tile use (and sInvC of prior mt)
            const int k0 = kt * 16;
            float4 a = *(const float4*)&Qb[(size_t)(row0 + lm) * DD + k0 + lk4];
            As[lk4 + 0][lm] = a.x; As[lk4 + 1][lm] = a.y;
            As[lk4 + 2][lm] = a.z; As[lk4 + 3][lm] = a.w;
            float4 c = *(const float4*)&Cb[(size_t)(col0 + lm) * DD + k0 + lk4];
            Bs[lk4 + 0][lm] = c.x; Bs[lk4 + 1][lm] = c.y;
            Bs[lk4 + 2][lm] = c.z; Bs[lk4 + 3][lm] = c.w;
            if (kt == 0 && tid < 64) sInvC[tid] = g_invc[b * NN + col0 + tid];
            __syncthreads();
#pragma unroll
            for (int kk = 0; kk < 16; kk++) {
                float4 av = *(const float4*)&As[kk][ty * 4];
                float4 bv = *(const float4*)&Bs[kk][tx * 4];
                acc[0][0] += av.x * bv.x; acc[0][1] += av.x * bv.y;
                acc[0][2] += av.x * bv.z; acc[0][3] += av.x * bv.w;
                acc[1][0] += av.y * bv.x; acc[1][1] += av.y * bv.y;
                acc[1][2] += av.y * bv.z; acc[1][3] += av.y * bv.w;
                acc[2][0] += av.z * bv.x; acc[2][1] += av.z * bv.y;
                acc[2][2] += av.z * bv.z; acc[2][3] += av.z * bv.w;
                acc[3][0] += av.w * bv.x; acc[3][1] += av.w * bv.y;
                acc[3][2] += av.w * bv.z; acc[3][3] += av.w * bv.w;
            }
        }
        // running max update (columns ascending -> strict > keeps first index)
#pragma unroll
        for (int j = 0; j < 4; j++) {
            const float ic = sInvC[tx * 4 + j];
            const int   cc = col0 + tx * 4 + j;
#pragma unroll
            for (int i = 0; i < 4; i++) {
                float s = acc[i][j] * ic;
                if (s > best[i]) { best[i] = s; bidx[i] = cc; }
            }
        }
    }

    // cross-thread (tx) reduction per row, lowest-index tie-break
#pragma unroll
    for (int i = 0; i < 4; i++) {
        sV[tid] = best[i]; sI[tid] = bidx[i];
        __syncthreads();
        for (int o = 8; o > 0; o >>= 1) {
            if (tx < o) {
                float v2 = sV[tid + o]; int i2 = sI[tid + o];
                float v1 = sV[tid];     int i1 = sI[tid];
                if (v2 > v1 || (v2 == v1 && i2 < i1)) { sV[tid] = v2; sI[tid] = i2; }
            }
            __syncthreads();
        }
        if (tx == 0) {
            int r = row0 + ty * 4 + i;
            g_maxs[b * NN + r] = sV[tid] * g_invq[b * NN + r];
            g_maxi[b * NN + r] = sI[tid];
        }
        __syncthreads();
    }
}

// ---------------------------------------------------------------------------
// Kernel C: gather + sigmoid blend epilogue. One block per (b,n) row.
// out layout: [reuse_map (B*N)] [reuse_input (B*N*D)] [reuse_value (B*N*D)]
// ---------------------------------------------------------------------------
__global__ __launch_bounds__(192) void blend_kernel(
    const float* __restrict__ Qi, const float* __restrict__ Qv,
    const float* __restrict__ Ci, const float* __restrict__ Cv,
    const float* __restrict__ thr_raw, float* __restrict__ out) {
    const int r = blockIdx.x;            // b*NN + n
    const int b = r / NN;
    const int n = r - b * NN;
    const int t = threadIdx.x;           // 0..191, one float4 each

    const float score = g_maxs[r];
    const int   idx   = g_maxi[r];
    const float thr   = 1.f / (1.f + expf(-thr_raw[n]));
    const float rm    = 1.f / (1.f + expf(-40.f * (score - thr)));
    const float om    = 1.f - rm;

    const float4* qi = (const float4*)(Qi + (size_t)r * DD);
    const float4* qv = (const float4*)(Qv + (size_t)r * DD);
    const float4* ci = (const float4*)(Ci + ((size_t)b * NN + idx) * DD);
    const float4* cv = (const float4*)(Cv + ((size_t)b * NN + idx) * DD);
    float4* oi = (float4*)(out + ROWS + (size_t)r * DD);
    float4* ov = (float4*)(out + ROWS + (size_t)ROWS * DD + (size_t)r * DD);

    float4 a = qi[t], c = ci[t];
    oi[t] = make_float4(om * a.x + rm * c.x, om * a.y + rm * c.y,
                        om * a.z + rm * c.z, om * a.w + rm * c.w);
    float4 av = qv[t], cvv = cv[t];
    ov[t] = make_float4(om * av.x + rm * cvv.x, om * av.y + rm * cvv.y,
                        om * av.z + rm * cvv.z, om * av.w + rm * cvv.w);
    if (t == 0) out[r] = rm;
}

// ---------------------------------------------------------------------------
extern "C" void kernel_launch(void* const* d_in, const int* in_sizes, int n_in,
                              void* d_out, int out_size) {
    const float* Qi = (const float*)d_in[0];  // query_input
    const float* Qv = (const float*)d_in[1];  // query_value
    const float* Ci = (const float*)d_in[2];  // cached_input
    const float* Cv = (const float*)d_in[3];  // cached_value
    const float* Th = (const float*)d_in[4];  // sim_threshold
    float* out = (float*)d_out;

    invnorm_kernel<<<(2 * ROWS) / 8, 256>>>(Qi, Ci);
    dim3 grid(NN / 64, BB);
    simargmax_kernel<<<grid, 256>>>(Qi, Ci);
    blend_kernel<<<ROWS, 192>>>(Qi, Qv, Ci, Cv, Th, out);
}

// round 4
// speedup vs baseline: 4.0910x; 4.0910x over previous
#include <cuda_runtime.h>
#include <cuda_bf16.h>
#include <cstdint>

#define BB 16
#define NN 2048
#define DD 768
#define ROWS (BB*NN)

#define KC 32                 // k elems per chunk
#define NCH (DD/KC)           // 24 chunks per ntile
#define NTPC 4                // ntiles per CTA
#define TOT_IT (NTPC*NCH)     // 96
#define NSTAGE 4
#define SUB 8192              // one 128x32 bf16 sub-buffer (swizzled)
#define STAGE (4*SUB)         // Ahi, Alo, Bhi, Blo
#define SMEM_DYN (NSTAGE*STAGE + 128*8)   // 132 KB

// ---- scratch (allocation-free rule: __device__ globals) --------------------
__device__ __align__(16) __nv_bfloat16 g_Qs[(size_t)ROWS*2*DD];  // [row][hi|lo][768]
__device__ __align__(16) __nv_bfloat16 g_Cs[(size_t)ROWS*2*DD];
__device__ float g_invq[ROWS];
__device__ unsigned long long g_pack[ROWS];

// ---------------------------------------------------------------------------
__device__ __forceinline__ uint32_t smem_u32(const void* p) {
    uint32_t a;
    asm("{ .reg .u64 t; cvta.to.shared.u64 t, %1; cvt.u32.u64 %0, t; }" : "=r"(a) : "l"(p));
    return a;
}
// swizzled offset inside one 128-row x 64B sub-buffer: pairs of rows share a
// 128B line; 16B pieces XOR-permuted by line index -> conflict-free LDSM + STS.
__device__ __forceinline__ uint32_t swoff(int row, int piece) {
    return (uint32_t)(((row >> 1) * 128) +
                      ((((((row & 1) << 2) | piece)) ^ ((row >> 1) & 7)) << 4));
}
__device__ __forceinline__ unsigned long long packsc(float v, int col) {
    uint32_t b = __float_as_uint(v);
    uint32_t key = (b & 0x80000000u) ? ~b : (b | 0x80000000u);
    return ((unsigned long long)key << 32) | (uint32_t)(2047 - col);
}

#define LDSM4(r, addr) \
    asm volatile("ldmatrix.sync.aligned.m8n8.x4.shared.b16 {%0,%1,%2,%3}, [%4];" \
        : "=r"((r)[0]), "=r"((r)[1]), "=r"((r)[2]), "=r"((r)[3]) : "r"(addr))

#define MMA16816(d, a, b) \
    asm volatile("mma.sync.aligned.m16n8k16.row.col.f32.bf16.bf16.f32 " \
        "{%0,%1,%2,%3}, {%4,%5,%6,%7}, {%8,%9}, {%0,%1,%2,%3};" \
        : "+f"((d)[0]), "+f"((d)[1]), "+f"((d)[2]), "+f"((d)[3]) \
        : "r"((a)[0]), "r"((a)[1]), "r"((a)[2]), "r"((a)[3]), "r"((b)[0]), "r"((b)[1]))

#define CP_ASYNC16(dst, src) \
    asm volatile("cp.async.cg.shared.global [%0], [%1], 16;" :: "r"(dst), "l"(src))
#define CP_COMMIT() asm volatile("cp.async.commit_group;" ::: "memory")
#define CP_WAIT2()  asm volatile("cp.async.wait_group 2;" ::: "memory")

// ---------------------------------------------------------------------------
// Prepass: per row: sumsq -> refined rsqrt; C rows scaled by 1/||c||; split
// f = hi + lo (bf16 each); also init g_invq / g_pack.
// grid (ROWS, 2): y==0 Q side, y==1 C side. block 128.
// ---------------------------------------------------------------------------
__global__ __launch_bounds__(128) void prep_kernel(const float* __restrict__ Qi,
                                                   const float* __restrict__ Ci) {
    const int r = blockIdx.x;
    const bool isC = (blockIdx.y != 0);
    __shared__ float row[DD];
    __shared__ float wsum[4];
    __shared__ float s_sc;
    const float* src = (isC ? Ci : Qi) + (size_t)r * DD;
    const int t = threadIdx.x;
    float ss = 0.f;
#pragma unroll
    for (int i = 0; i < DD / 128; i++) {
        float v = src[t + 128 * i]; row[t + 128 * i] = v; ss += v * v;
    }
#pragma unroll
    for (int o = 16; o > 0; o >>= 1) ss += __shfl_xor_sync(~0u, ss, o);
    if ((t & 31) == 0) wsum[t >> 5] = ss;
    __syncthreads();
    if (t == 0) {
        float s = wsum[0] + wsum[1] + wsum[2] + wsum[3];
        float inv = rsqrtf(s);
        inv = inv * (1.5f - 0.5f * s * inv * inv);  // Newton -> ~fp32 exact
        if (isC) s_sc = inv;
        else { s_sc = 1.f; g_invq[r] = inv; g_pack[r] = 0ull; }
    }
    __syncthreads();
    const float sc = s_sc;
    __nv_bfloat16* dst = (isC ? g_Cs : g_Qs) + (size_t)r * 2 * DD;
#pragma unroll
    for (int i = 0; i < DD / 128; i++) {
        int k = t + 128 * i;
        float f = row[k] * sc;
        __nv_bfloat16 hi = __float2bfloat16(f);
        __nv_bfloat16 lo = __float2bfloat16(f - __bfloat162float(hi));
        dst[k] = hi;
        dst[DD + k] = lo;
    }
}

// ---------------------------------------------------------------------------
// GEMM-argmax: grid (16 mtiles, 4 ngroups, 16 batches) = 1024 CTAs, 256 thr.
// Each CTA: 128 q-rows x 4 n-tiles of 128, K' = 768 in 24 chunks of 32.
// Per chunk: load Ahi/Alo/Bhi/Blo once; 3 mma passes (hh, hl, lh).
// ---------------------------------------------------------------------------
__global__ __launch_bounds__(256, 1) void gemm_kernel() {
    extern __shared__ __align__(1024) unsigned char smem[];
    const uint32_t sb = smem_u32(smem);
    unsigned long long* table = (unsigned long long*)(smem + NSTAGE * STAGE);

    const int mt = blockIdx.x, ngrp = blockIdx.y, b = blockIdx.z;
    const int tid = threadIdx.x, wid = tid >> 5, lane = tid & 31;
    const int wm = wid & 1, wn = wid >> 1;
    const int qrow0 = b * NN + mt * 128;
    const int crow0 = b * NN + ngrp * (NTPC * 128);

    if (tid < 128) table[tid] = 0ull;

    float acc[4][4][4];
#pragma unroll
    for (int i = 0; i < 4; i++)
#pragma unroll
        for (int j = 0; j < 4; j++)
#pragma unroll
            for (int c = 0; c < 4; c++) acc[i][j][c] = 0.f;

    // ---- chunk issue helper (lambda-ish via macro-free inline) ----
    auto issue_chunk = [&](int it) {
        const int nt = it / NCH, kc = it - nt * NCH;
        const uint32_t stage = sb + (uint32_t)(it & (NSTAGE - 1)) * STAGE;
#pragma unroll
        for (int sub = 0; sub < 4; sub++) {
            const int split = sub & 1;
            const bool isB = sub >= 2;
            const __nv_bfloat16* base = isB ? g_Cs : g_Qs;
            const int row0 = isB ? (crow0 + nt * 128) : qrow0;
#pragma unroll
            for (int pp = 0; pp < 2; pp++) {
                const int p = tid * 2 + pp;
                const int row = p >> 2, q = p & 3;
                const void* src = base + ((size_t)(row0 + row) * 2 + split) * DD
                                       + kc * KC + q * 8;
                const uint32_t dst = stage + sub * SUB + swoff(row, q);
                CP_ASYNC16(dst, src);
            }
        }
        CP_COMMIT();
    };

    // prologue
    issue_chunk(0); issue_chunk(1); issue_chunk(2);

    for (int it = 0; it < TOT_IT; it++) {
        CP_WAIT2();
        __syncthreads();
        const uint32_t abase = sb + (uint32_t)(it & (NSTAGE - 1)) * STAGE;
        // ---- compute chunk ----
#pragma unroll
        for (int kk = 0; kk < 2; kk++) {
            uint32_t ah[4][4], al[4][4], bh[4][2], bl[4][2];
            const int lr = lane & 15, lp = lane >> 4;
#pragma unroll
            for (int i = 0; i < 4; i++) {
                const uint32_t ao = swoff(wm * 64 + i * 16 + lr, kk * 2 + lp);
                LDSM4(ah[i], abase + ao);
                LDSM4(al[i], abase + SUB + ao);
            }
#pragma unroll
            for (int jp = 0; jp < 2; jp++) {
                const int nrow = wn * 32 + (jp * 2 + (lane >> 4)) * 8 + (lane & 7);
                const int piece = kk * 2 + ((lane >> 3) & 1);
                const uint32_t bo = swoff(nrow, piece);
                uint32_t r4[4];
                LDSM4(r4, abase + 2 * SUB + bo);
                bh[jp*2][0]=r4[0]; bh[jp*2][1]=r4[1]; bh[jp*2+1][0]=r4[2]; bh[jp*2+1][1]=r4[3];
                LDSM4(r4, abase + 3 * SUB + bo);
                bl[jp*2][0]=r4[0]; bl[jp*2][1]=r4[1]; bl[jp*2+1][0]=r4[2]; bl[jp*2+1][1]=r4[3];
            }
#pragma unroll
            for (int i = 0; i < 4; i++)
#pragma unroll
                for (int j = 0; j < 4; j++) {
                    MMA16816(acc[i][j], ah[i], bh[j]);
                    MMA16816(acc[i][j], ah[i], bl[j]);
                    MMA16816(acc[i][j], al[i], bh[j]);
                }
        }
        if (it + 3 < TOT_IT) issue_chunk(it + 3);
        // ---- per-ntile epilogue ----
        if ((it % NCH) == NCH - 1) {
            const int nt = it / NCH;
            const int colbase = (ngrp * NTPC + nt) * 128 + wn * 32 + (lane & 3) * 2;
#pragma unroll
            for (int i = 0; i < 4; i++)
#pragma unroll
                for (int half = 0; half < 2; half++) {
                    float bv = -3.0e38f; int bc = 0;
#pragma unroll
                    for (int j = 0; j < 4; j++) {
                        const int c0 = colbase + j * 8;
                        float v0 = acc[i][j][half * 2 + 0];
                        if (v0 > bv) { bv = v0; bc = c0; }
                        float v1 = acc[i][j][half * 2 + 1];
                        if (v1 > bv) { bv = v1; bc = c0 + 1; }
                    }
#pragma unroll
                    for (int off = 1; off < 4; off <<= 1) {
                        float ov = __shfl_xor_sync(~0u, bv, off);
                        int   oc = __shfl_xor_sync(~0u, bc, off);
                        if (ov > bv || (ov == bv && oc < bc)) { bv = ov; bc = oc; }
                    }
                    if ((lane & 3) == 0) {
                        const int rloc = wm * 64 + i * 16 + half * 8 + (lane >> 2);
                        atomicMax(&table[rloc], packsc(bv, bc));
                    }
                }
#pragma unroll
            for (int i = 0; i < 4; i++)
#pragma unroll
                for (int j = 0; j < 4; j++)
#pragma unroll
                    for (int c = 0; c < 4; c++) acc[i][j][c] = 0.f;
        }
    }
    __syncthreads();
    if (tid < 128) atomicMax(&g_pack[qrow0 + tid], table[tid]);
}

// ---------------------------------------------------------------------------
// Blend epilogue: unpack (score,idx), gather, sigmoid blend.
// out layout: [reuse_map (B*N)] [reuse_input (B*N*D)] [reuse_value (B*N*D)]
// ---------------------------------------------------------------------------
__global__ __launch_bounds__(192) void blend_kernel(
    const float* __restrict__ Qi, const float* __restrict__ Qv,
    const float* __restrict__ Ci, const float* __restrict__ Cv,
    const float* __restrict__ thr_raw, float* __restrict__ out) {
    const int r = blockIdx.x;
    const int b = r / NN;
    const int n = r - b * NN;
    const int t = threadIdx.x;

    const unsigned long long p = g_pack[r];
    const uint32_t key = (uint32_t)(p >> 32);
    const uint32_t fb = (key & 0x80000000u) ? (key & 0x7FFFFFFFu) : ~key;
    const float score = __uint_as_float(fb) * g_invq[r];
    const int idx = 2047 - (int)(uint32_t)(p & 0xFFFFFFFFull);

    const float thr = 1.f / (1.f + expf(-thr_raw[n]));
    const float rm  = 1.f / (1.f + expf(-40.f * (score - thr)));
    const float om  = 1.f - rm;

    const float4* qi = (const float4*)(Qi + (size_t)r * DD);
    const float4* qv = (const float4*)(Qv + (size_t)r * DD);
    const float4* ci = (const float4*)(Ci + ((size_t)b * NN + idx) * DD);
    const float4* cv = (const float4*)(Cv + ((size_t)b * NN + idx) * DD);
    float4* oi = (float4*)(out + ROWS + (size_t)r * DD);
    float4* ov = (float4*)(out + ROWS + (size_t)ROWS * DD + (size_t)r * DD);

    float4 a = qi[t], c = ci[t];
    oi[t] = make_float4(om * a.x + rm * c.x, om * a.y + rm * c.y,
                        om * a.z + rm * c.z, om * a.w + rm * c.w);
    float4 av = qv[t], cvv = cv[t];
    ov[t] = make_float4(om * av.x + rm * cvv.x, om * av.y + rm * cvv.y,
                        om * av.z + rm * cvv.z, om * av.w + rm * cvv.w);
    if (t == 0) out[r] = rm;
}

// ---------------------------------------------------------------------------
extern "C" void kernel_launch(void* const* d_in, const int* in_sizes, int n_in,
                              void* d_out, int out_size) {
    const float* Qi = (const float*)d_in[0];
    const float* Qv = (const float*)d_in[1];
    const float* Ci = (const float*)d_in[2];
    const float* Cv = (const float*)d_in[3];
    const float* Th = (const float*)d_in[4];
    float* out = (float*)d_out;

    static int attr_set = 0;
    if (!attr_set) {
        cudaFuncSetAttribute(gemm_kernel,
                             cudaFuncAttributeMaxDynamicSharedMemorySize, SMEM_DYN);
        attr_set = 1;
    }

    prep_kernel<<<dim3(ROWS, 2), 128>>>(Qi, Ci);
    gemm_kernel<<<dim3(NN / 128, NN / 128 / NTPC, BB), 256, SMEM_DYN>>>();
    blend_kernel<<<ROWS, 192>>>(Qi, Qv, Ci, Cv, Th, out);
}

// round 5
// speedup vs baseline: 6.4347x; 1.5729x over previous
#include <cuda_runtime.h>
#include <cuda_bf16.h>
#include <cstdint>

#define BB 16
#define NN 2048
#define DD 768
#define ROWS (BB*NN)

#define KC 32                 // k elems per chunk
#define NCH (DD/KC)           // 24 chunks per ntile
#define NTPC 4                // ntiles per CTA
#define TOT_IT (NTPC*NCH)     // 96
#define NSTAGE 4
#define SUB 8192              // one 128x32 bf16 sub-buffer (swizzled)
#define STAGE (2*SUB)         // A hi, B hi
#define SMEM_DYN (NSTAGE*STAGE + 128*8)   // 66560
#define CAP 64
#define MARGIN 1.5e-3f

// ---- scratch (allocation-free rule: __device__ globals) --------------------
__device__ __align__(16) __nv_bfloat16 g_Qh[(size_t)ROWS*DD];  // bf16(q/||q||)
__device__ __align__(16) __nv_bfloat16 g_Ch[(size_t)ROWS*DD];  // bf16(c/||c||)
__device__ float g_invq[ROWS];
__device__ float g_invc[ROWS];
__device__ int   g_cnt[ROWS];
__device__ int   g_cand[(size_t)ROWS*CAP];

// ---------------------------------------------------------------------------
__device__ __forceinline__ uint32_t smem_u32(const void* p) {
    uint32_t a;
    asm("{ .reg .u64 t; cvta.to.shared.u64 t, %1; cvt.u32.u64 %0, t; }" : "=r"(a) : "l"(p));
    return a;
}
// swizzled offset inside one 128-row x 64B sub-buffer (conflict-free LDSM+STS)
__device__ __forceinline__ uint32_t swoff(int row, int piece) {
    return (uint32_t)(((row >> 1) * 128) +
                      ((((((row & 1) << 2) | piece)) ^ ((row >> 1) & 7)) << 4));
}
__device__ __forceinline__ unsigned long long packsc(float v, int col) {
    uint32_t b = __float_as_uint(v);
    uint32_t key = (b & 0x80000000u) ? ~b : (b | 0x80000000u);
    return ((unsigned long long)key << 32) | (uint32_t)(2047 - col);
}
__device__ __forceinline__ float unpack_score(unsigned long long p) {
    uint32_t key = (uint32_t)(p >> 32);
    uint32_t fb = (key & 0x80000000u) ? (key & 0x7FFFFFFFu) : ~key;
    return __uint_as_float(fb);
}

#define LDSM4(r, addr) \
    asm volatile("ldmatrix.sync.aligned.m8n8.x4.shared.b16 {%0,%1,%2,%3}, [%4];" \
        : "=r"((r)[0]), "=r"((r)[1]), "=r"((r)[2]), "=r"((r)[3]) : "r"(addr))

#define MMA16816(d, a, b) \
    asm volatile("mma.sync.aligned.m16n8k16.row.col.f32.bf16.bf16.f32 " \
        "{%0,%1,%2,%3}, {%4,%5,%6,%7}, {%8,%9}, {%0,%1,%2,%3};" \
        : "+f"((d)[0]), "+f"((d)[1]), "+f"((d)[2]), "+f"((d)[3]) \
        : "r"((a)[0]), "r"((a)[1]), "r"((a)[2]), "r"((a)[3]), "r"((b)[0]), "r"((b)[1]))

#define CP_ASYNC16(dst, src) \
    asm volatile("cp.async.cg.shared.global [%0], [%1], 16;" :: "r"(dst), "l"(src))
#define CP_COMMIT() asm volatile("cp.async.commit_group;" ::: "memory")
#define CP_WAIT2()  asm volatile("cp.async.wait_group 2;" ::: "memory")

// ---------------------------------------------------------------------------
// Prepass: per row: refined rsqrt norm; write bf16(normalized row); store
// invq / invc; zero candidate counters. grid (ROWS, 2): y==0 Q, y==1 C.
// ---------------------------------------------------------------------------
__global__ __launch_bounds__(128) void prep_kernel(const float* __restrict__ Qi,
                                                   const float* __restrict__ Ci) {
    const int r = blockIdx.x;
    const bool isC = (blockIdx.y != 0);
    __shared__ float row[DD];
    __shared__ float wsum[4];
    __shared__ float s_sc;
    const float* src = (isC ? Ci : Qi) + (size_t)r * DD;
    const int t = threadIdx.x;
    float ss = 0.f;
#pragma unroll
    for (int i = 0; i < DD / 128; i++) {
        float v = src[t + 128 * i]; row[t + 128 * i] = v; ss += v * v;
    }
#pragma unroll
    for (int o = 16; o > 0; o >>= 1) ss += __shfl_xor_sync(~0u, ss, o);
    if ((t & 31) == 0) wsum[t >> 5] = ss;
    __syncthreads();
    if (t == 0) {
        float s = wsum[0] + wsum[1] + wsum[2] + wsum[3];
        float inv = rsqrtf(s);
        inv = inv * (1.5f - 0.5f * s * inv * inv);  // Newton -> ~fp32 exact
        s_sc = inv;
        if (isC) g_invc[r] = inv;
        else { g_invq[r] = inv; g_cnt[r] = 0; }
    }
    __syncthreads();
    const float sc = s_sc;
    __nv_bfloat16* dst = (isC ? g_Ch : g_Qh) + (size_t)r * DD;
#pragma unroll
    for (int i = 0; i < DD / 128; i++) {
        int k = t + 128 * i;
        dst[k] = __float2bfloat16(row[k] * sc);
    }
}

// ---------------------------------------------------------------------------
// Approx GEMM + margin candidate collection.
// grid (16 mtiles, 4 ngroups, 16 batches) = 1024 CTAs, 256 thr, 2 CTA/SM.
// Each CTA: 128 q-rows x 4 n-tiles of 128 cols, K=768 in 24 chunks of 32.
// Per-CTA running max table (packed) in smem; columns within MARGIN of the
// running local max are appended to the per-row global candidate list.
// ---------------------------------------------------------------------------
__global__ __launch_bounds__(256, 2) void gemm_kernel() {
    extern __shared__ __align__(1024) unsigned char smem[];
    const uint32_t sb = smem_u32(smem);
    unsigned long long* table = (unsigned long long*)(smem + NSTAGE * STAGE);

    const int mt = blockIdx.x, ngrp = blockIdx.y, b = blockIdx.z;
    const int tid = threadIdx.x, wid = tid >> 5, lane = tid & 31;
    const int wm = wid & 1, wn = wid >> 1;
    const int qrow0 = b * NN + mt * 128;
    const int crow0 = b * NN + ngrp * (NTPC * 128);

    if (tid < 128) table[tid] = 0ull;

    float acc[4][4][4];
#pragma unroll
    for (int i = 0; i < 4; i++)
#pragma unroll
        for (int j = 0; j < 4; j++)
#pragma unroll
            for (int c = 0; c < 4; c++) acc[i][j][c] = 0.f;

    auto issue_chunk = [&](int it) {
        const int nt = it / NCH, kc = it - nt * NCH;
        const uint32_t stage = sb + (uint32_t)(it & (NSTAGE - 1)) * STAGE;
#pragma unroll
        for (int sub = 0; sub < 2; sub++) {
            const bool isB = (sub != 0);
            const __nv_bfloat16* base = isB ? g_Ch : g_Qh;
            const int row0 = isB ? (crow0 + nt * 128) : qrow0;
#pragma unroll
            for (int pp = 0; pp < 2; pp++) {
                const int p = tid * 2 + pp;
                const int row = p >> 2, q = p & 3;
                const void* src = base + (size_t)(row0 + row) * DD + kc * KC + q * 8;
                const uint32_t dst = stage + sub * SUB + swoff(row, q);
                CP_ASYNC16(dst, src);
            }
        }
        CP_COMMIT();
    };

    issue_chunk(0); issue_chunk(1); issue_chunk(2);

    for (int it = 0; it < TOT_IT; it++) {
        CP_WAIT2();
        __syncthreads();
        const uint32_t abase = sb + (uint32_t)(it & (NSTAGE - 1)) * STAGE;
#pragma unroll
        for (int kk = 0; kk < 2; kk++) {
            uint32_t ah[4][4], bh[4][2];
            const int lr = lane & 15, lp = lane >> 4;
#pragma unroll
            for (int i = 0; i < 4; i++) {
                const uint32_t ao = swoff(wm * 64 + i * 16 + lr, kk * 2 + lp);
                LDSM4(ah[i], abase + ao);
            }
#pragma unroll
            for (int jp = 0; jp < 2; jp++) {
                const int nrow = wn * 32 + (jp * 2 + (lane >> 4)) * 8 + (lane & 7);
                const int piece = kk * 2 + ((lane >> 3) & 1);
                uint32_t r4[4];
                LDSM4(r4, abase + SUB + swoff(nrow, piece));
                bh[jp*2][0]=r4[0]; bh[jp*2][1]=r4[1]; bh[jp*2+1][0]=r4[2]; bh[jp*2+1][1]=r4[3];
            }
#pragma unroll
            for (int i = 0; i < 4; i++)
#pragma unroll
                for (int j = 0; j < 4; j++)
                    MMA16816(acc[i][j], ah[i], bh[j]);
        }
        if (it + 3 < TOT_IT) issue_chunk(it + 3);

        if ((it % NCH) == NCH - 1) {
            const int nt = it / NCH;
            const int colbase = (ngrp * NTPC + nt) * 128 + wn * 32 + (lane & 3) * 2;
            // phase 1: update running local max table
#pragma unroll
            for (int i = 0; i < 4; i++)
#pragma unroll
                for (int half = 0; half < 2; half++) {
                    float bv = -3.0e38f; int bc = 0;
#pragma unroll
                    for (int j = 0; j < 4; j++) {
                        const int c0 = colbase + j * 8;
                        float v0 = acc[i][j][half * 2 + 0];
                        if (v0 > bv) { bv = v0; bc = c0; }
                        float v1 = acc[i][j][half * 2 + 1];
                        if (v1 > bv) { bv = v1; bc = c0 + 1; }
                    }
#pragma unroll
                    for (int off = 1; off < 4; off <<= 1) {
                        float ov = __shfl_xor_sync(~0u, bv, off);
                        int   oc = __shfl_xor_sync(~0u, bc, off);
                        if (ov > bv || (ov == bv && oc < bc)) { bv = ov; bc = oc; }
                    }
                    if ((lane & 3) == 0) {
                        const int rloc = wm * 64 + i * 16 + half * 8 + (lane >> 2);
                        atomicMax(&table[rloc], packsc(bv, bc));
                    }
                }
            __syncthreads();
            // phase 2: append candidates within MARGIN of running local max
#pragma unroll
            for (int i = 0; i < 4; i++)
#pragma unroll
                for (int half = 0; half < 2; half++) {
                    const int rloc = wm * 64 + i * 16 + half * 8 + (lane >> 2);
                    const float cut = unpack_score(table[rloc]) - MARGIN;
                    const int rg = qrow0 + rloc;
#pragma unroll
                    for (int j = 0; j < 4; j++)
#pragma unroll
                        for (int c = 0; c < 2; c++) {
                            float v = acc[i][j][half * 2 + c];
                            if (v >= cut) {
                                int slot = atomicAdd(&g_cnt[rg], 1);
                                if (slot < CAP)
                                    g_cand[(size_t)rg * CAP + slot] = colbase + j * 8 + c;
                            }
                        }
                }
#pragma unroll
            for (int i = 0; i < 4; i++)
#pragma unroll
                for (int j = 0; j < 4; j++)
#pragma unroll
                    for (int c = 0; c < 4; c++) acc[i][j][c] = 0.f;
        }
    }
}

// ---------------------------------------------------------------------------
// Fused exact rescore + blend. One block (192 thr) per row.
// Rescores candidates in fp32 (q_raw . c_raw * invq * invc), exact argmax
// (tie: lowest idx), then sigmoid blend + output.
// out layout: [reuse_map (B*N)] [reuse_input (B*N*D)] [reuse_value (B*N*D)]
// ---------------------------------------------------------------------------
__global__ __launch_bounds__(192) void rescore_blend_kernel(
    const float* __restrict__ Qi, const float* __restrict__ Qv,
    const float* __restrict__ Ci, const float* __restrict__ Cv,
    const float* __restrict__ thr_raw, float* __restrict__ out) {
    const int r = blockIdx.x;
    const int b = r >> 11;
    const int n = r & (NN - 1);
    const int t = threadIdx.x, wid = t >> 5, lane = t & 31;

    __shared__ __align__(16) float q[DD];
    __shared__ unsigned long long wbest[6];
    __shared__ float s_rm;
    __shared__ int s_idx;

    ((float4*)q)[t] = ((const float4*)(Qi + (size_t)r * DD))[t];
    __syncthreads();

    int cnt = g_cnt[r]; if (cnt > CAP) cnt = CAP;
    const float invq = g_invq[r];
    unsigned long long best = 0ull;
    for (int ci = wid; ci < cnt; ci += 6) {
        const int idx = g_cand[(size_t)r * CAP + ci];
        const float4* crow = (const float4*)(Ci + ((size_t)(b * NN + idx)) * DD);
        float s = 0.f;
#pragma unroll
        for (int u = 0; u < 6; u++) {
            float4 cv = crow[lane + 32 * u];
            float4 qv = ((const float4*)q)[lane + 32 * u];
            s += cv.x * qv.x + cv.y * qv.y + cv.z * qv.z + cv.w * qv.w;
        }
#pragma unroll
        for (int o = 16; o > 0; o >>= 1) s += __shfl_xor_sync(~0u, s, o);
        if (lane == 0) {
            unsigned long long p = packsc(s * invq * g_invc[b * NN + idx], idx);
            if (p > best) best = p;
        }
    }
    if (lane == 0) wbest[wid] = best;
    __syncthreads();
    if (t == 0) {
        unsigned long long B = 0ull;
#pragma unroll
        for (int w = 0; w < 6; w++) if (wbest[w] > B) B = wbest[w];
        const float score = unpack_score(B);
        const int idx = 2047 - (int)(uint32_t)(B & 0xFFFFFFFFull);
        const float thr = 1.f / (1.f + expf(-thr_raw[n]));
        const float rm  = 1.f / (1.f + expf(-40.f * (score - thr)));
        s_rm = rm; s_idx = idx;
        out[r] = rm;
    }
    __syncthreads();
    const float rm = s_rm, om = 1.f - rm;
    const int idx = s_idx;
    const float4* qv = (const float4*)(Qv + (size_t)r * DD);
    const float4* ci = (const float4*)(Ci + ((size_t)b * NN + idx) * DD);
    const float4* cv = (const float4*)(Cv + ((size_t)b * NN + idx) * DD);
    float4* oi = (float4*)(out + ROWS + (size_t)r * DD);
    float4* ov = (float4*)(out + ROWS + (size_t)ROWS * DD + (size_t)r * DD);

    float4 a = ((const float4*)q)[t], c = ci[t];
    oi[t] = make_float4(om * a.x + rm * c.x, om * a.y + rm * c.y,
                        om * a.z + rm * c.z, om * a.w + rm * c.w);
    float4 av = qv[t], cvv = cv[t];
    ov[t] = make_float4(om * av.x + rm * cvv.x, om * av.y + rm * cvv.y,
                        om * av.z + rm * cvv.z, om * av.w + rm * cvv.w);
}

// ---------------------------------------------------------------------------
extern "C" void kernel_launch(void* const* d_in, const int* in_sizes, int n_in,
                              void* d_out, int out_size) {
    const float* Qi = (const float*)d_in[0];
    const float* Qv = (const float*)d_in[1];
    const float* Ci = (const float*)d_in[2];
    const float* Cv = (const float*)d_in[3];
    const float* Th = (const float*)d_in[4];
    float* out = (float*)d_out;

    cudaFuncSetAttribute(gemm_kernel,
                         cudaFuncAttributeMaxDynamicSharedMemorySize, SMEM_DYN);

    prep_kernel<<<dim3(ROWS, 2), 128>>>(Qi, Ci);
    gemm_kernel<<<dim3(NN / 128, NN / 128 / NTPC, BB), 256, SMEM_DYN>>>();
    rescore_blend_kernel<<<ROWS, 192>>>(Qi, Qv, Ci, Cv, Th, out);
}

// round 6
// speedup vs baseline: 6.8625x; 1.0665x over previous
#include <cuda_runtime.h>
#include <cuda_fp16.h>
#include <cstdint>

#define BB 16
#define NN 2048
#define DD 768
#define ROWS (BB*NN)

#define KC 32                  // k elems per chunk
#define NCH (DD/KC)            // 24 chunks per tile item
#define NITEMS (BB*16*16)      // 4096 (b, mt, nt) 128x128 tiles
#define GRID 296               // 148 SMs x 2 CTA/SM (persistent-ish)
#define NSTAGE 6
#define SUB 8192               // one 128x32 fp16 sub-buffer (swizzled)
#define STAGE (2*SUB)          // A, B
#define SMEM_DYN (NSTAGE*STAGE + 128*8 + 128*4)   // 99840
#define CAP 64
#define MARGIN 4e-4f

// ---- scratch (allocation-free rule: __device__ globals) --------------------
__device__ __align__(16) __half g_Qh[(size_t)ROWS*DD];  // fp16(q/||q||)
__device__ __align__(16) __half g_Ch[(size_t)ROWS*DD];  // fp16(c/||c||)
__device__ float g_invq[ROWS];
__device__ float g_invc[ROWS];
__device__ unsigned long long g_gmax[ROWS];
__device__ int   g_cnt[ROWS];
__device__ int   g_cand[(size_t)ROWS*CAP];

// ---------------------------------------------------------------------------
__device__ __forceinline__ uint32_t smem_u32(const void* p) {
    uint32_t a;
    asm("{ .reg .u64 t; cvta.to.shared.u64 t, %1; cvt.u32.u64 %0, t; }" : "=r"(a) : "l"(p));
    return a;
}
// swizzled offset inside one 128-row x 64B sub-buffer (conflict-free LDSM+STS)
__device__ __forceinline__ uint32_t swoff(int row, int piece) {
    return (uint32_t)(((row >> 1) * 128) +
                      ((((((row & 1) << 2) | piece)) ^ ((row >> 1) & 7)) << 4));
}
__device__ __forceinline__ unsigned long long packsc(float v, int col) {
    uint32_t b = __float_as_uint(v);
    uint32_t key = (b & 0x80000000u) ? ~b : (b | 0x80000000u);
    return ((unsigned long long)key << 32) | (uint32_t)(2047 - col);
}
__device__ __forceinline__ float unpack_score(unsigned long long p) {
    uint32_t key = (uint32_t)(p >> 32);
    uint32_t fb = (key & 0x80000000u) ? (key & 0x7FFFFFFFu) : ~key;
    return __uint_as_float(fb);
}

#define LDSM4(r, addr) \
    asm volatile("ldmatrix.sync.aligned.m8n8.x4.shared.b16 {%0,%1,%2,%3}, [%4];" \
        : "=r"((r)[0]), "=r"((r)[1]), "=r"((r)[2]), "=r"((r)[3]) : "r"(addr))

#define MMA16816(d, a, b) \
    asm volatile("mma.sync.aligned.m16n8k16.row.col.f32.f16.f16.f32 " \
        "{%0,%1,%2,%3}, {%4,%5,%6,%7}, {%8,%9}, {%0,%1,%2,%3};" \
        : "+f"((d)[0]), "+f"((d)[1]), "+f"((d)[2]), "+f"((d)[3]) \
        : "r"((a)[0]), "r"((a)[1]), "r"((a)[2]), "r"((a)[3]), "r"((b)[0]), "r"((b)[1]))

#define CP_ASYNC16(dst, src) \
    asm volatile("cp.async.cg.shared.global [%0], [%1], 16;" :: "r"(dst), "l"(src))
#define CP_COMMIT() asm volatile("cp.async.commit_group;" ::: "memory")
#define CP_WAIT4()  asm volatile("cp.async.wait_group 4;" ::: "memory")

// ---------------------------------------------------------------------------
// Prepass: per row: refined rsqrt norm; write fp16(normalized row); store
// invq / invc; zero g_gmax / g_cnt. grid (ROWS, 2): y==0 Q, y==1 C. 192 thr.
// ---------------------------------------------------------------------------
__global__ __launch_bounds__(192) void prep_kernel(const float* __restrict__ Qi,
                                                   const float* __restrict__ Ci) {
    const int r = blockIdx.x;
    const bool isC = (blockIdx.y != 0);
    __shared__ __align__(16) float row[DD];
    __shared__ float wsum[6];
    __shared__ float s_sc;
    const int t = threadIdx.x;
    float4 v = ((const float4*)((isC ? Ci : Qi) + (size_t)r * DD))[t];
    ((float4*)row)[t] = v;
    float ss = v.x * v.x + v.y * v.y + v.z * v.z + v.w * v.w;
#pragma unroll
    for (int o = 16; o > 0; o >>= 1) ss += __shfl_xor_sync(~0u, ss, o);
    if ((t & 31) == 0) wsum[t >> 5] = ss;
    __syncthreads();
    if (t == 0) {
        float s = wsum[0] + wsum[1] + wsum[2] + wsum[3] + wsum[4] + wsum[5];
        float inv = rsqrtf(s);
        inv = inv * (1.5f - 0.5f * s * inv * inv);  // Newton -> ~fp32 exact
        s_sc = inv;
        if (isC) g_invc[r] = inv;
        else { g_invq[r] = inv; g_cnt[r] = 0; g_gmax[r] = 0ull; }
    }
    __syncthreads();
    const float sc = s_sc;
    __half* dst = (isC ? g_Ch : g_Qh) + (size_t)r * DD;
    __half2 h0 = __floats2half2_rn(row[4 * t + 0] * sc, row[4 * t + 1] * sc);
    __half2 h1 = __floats2half2_rn(row[4 * t + 2] * sc, row[4 * t + 3] * sc);
    uint2 u;
    u.x = *(uint32_t*)&h0; u.y = *(uint32_t*)&h1;
    ((uint2*)dst)[t] = u;
}

// ---------------------------------------------------------------------------
// Persistent approx GEMM + margin candidate collection.
// 296 CTAs, 256 thr, 2 CTA/SM. Items = 4096 (b, mt, nt) 128x128 tiles,
// strided: item = cta + k*GRID. 6-stage cp.async pipeline, K in 24 chunks.
// Epilogue per item: tile max -> global running row max (atomicMax) ->
// cut = globalmax - MARGIN -> append candidate cols.
// ---------------------------------------------------------------------------
__global__ __launch_bounds__(256, 2) void gemm_kernel() {
    extern __shared__ __align__(1024) unsigned char smem[];
    const uint32_t sb = smem_u32(smem);
    unsigned long long* table = (unsigned long long*)(smem + NSTAGE * STAGE);
    float* tableF = (float*)(smem + NSTAGE * STAGE + 128 * 8);

    const int cta = blockIdx.x;
    const int tid = threadIdx.x, wid = tid >> 5, lane = tid & 31;
    const int wm = wid & 1, wn = wid >> 1;

    const int nit = (NITEMS - cta + GRID - 1) / GRID;
    const int nch_tot = nit * NCH;

    if (tid < 128) table[tid] = 0ull;
    __syncthreads();

    float acc[4][4][4];
#pragma unroll
    for (int i = 0; i < 4; i++)
#pragma unroll
        for (int j = 0; j < 4; j++)
#pragma unroll
            for (int c = 0; c < 4; c++) acc[i][j][c] = 0.f;

    auto issue_chunk = [&](int f, int stage_idx) {
        const int il = f / NCH, kc = f - il * NCH;
        const int item = cta + il * GRID;
        const int b = item >> 8, mt = (item >> 4) & 15, nt = item & 15;
        const uint32_t stage = sb + (uint32_t)stage_idx * STAGE;
        const __half* abase = g_Qh + ((size_t)(b * NN + mt * 128)) * DD + kc * KC;
        const __half* bbase = g_Ch + ((size_t)(b * NN + nt * 128)) * DD + kc * KC;
#pragma unroll
        for (int pp = 0; pp < 2; pp++) {
            const int p = tid * 2 + pp;
            const int row = p >> 2, q = p & 3;
            const uint32_t so = swoff(row, q);
            CP_ASYNC16(stage + so,       abase + (size_t)row * DD + q * 8);
            CP_ASYNC16(stage + SUB + so, bbase + (size_t)row * DD + q * 8);
        }
        CP_COMMIT();
    };

    // prologue: 5 chunks into stages 0..4
#pragma unroll
    for (int j = 0; j < 5; j++) issue_chunk(j, j);

    int cs = 0, is = 5;   // consume / issue stage (mod 6, rolling)
    for (int f = 0; f < nch_tot; f++) {
        CP_WAIT4();
        __syncthreads();
        const uint32_t abase = sb + (uint32_t)cs * STAGE;
#pragma unroll
        for (int kk = 0; kk < 2; kk++) {
            uint32_t ah[4][4], bh[4][2];
            const int lr = lane & 15, lp = lane >> 4;
#pragma unroll
            for (int i = 0; i < 4; i++)
                LDSM4(ah[i], abase + swoff(wm * 64 + i * 16 + lr, kk * 2 + lp));
#pragma unroll
            for (int jp = 0; jp < 2; jp++) {
                const int nrow = wn * 32 + (jp * 2 + (lane >> 4)) * 8 + (lane & 7);
                const int piece = kk * 2 + ((lane >> 3) & 1);
                uint32_t r4[4];
                LDSM4(r4, abase + SUB + swoff(nrow, piece));
                bh[jp*2][0]=r4[0]; bh[jp*2][1]=r4[1]; bh[jp*2+1][0]=r4[2]; bh[jp*2+1][1]=r4[3];
            }
#pragma unroll
            for (int i = 0; i < 4; i++)
#pragma unroll
                for (int j = 0; j < 4; j++)
                    MMA16816(acc[i][j], ah[i], bh[j]);
        }
        if (f + 5 < nch_tot) { issue_chunk(f + 5, is); is = (is == 5) ? 0 : is + 1; }
        cs = (cs == 5) ? 0 : cs + 1;

        const int il = f / NCH;
        if (f - il * NCH == NCH - 1) {
            const int item = cta + il * GRID;
            const int b = item >> 8, mt = (item >> 4) & 15, nt = item & 15;
            const int qrow0 = b * NN + mt * 128;
            const int colbase = nt * 128 + wn * 32 + (lane & 3) * 2;
            // phase 1: per-row tile max into smem table
#pragma unroll
            for (int i = 0; i < 4; i++)
#pragma unroll
                for (int half = 0; half < 2; half++) {
                    float bv = -3.0e38f; int bc = 0;
#pragma unroll
                    for (int j = 0; j < 4; j++) {
                        const int c0 = colbase + j * 8;
                        float v0 = acc[i][j][half * 2 + 0];
                        if (v0 > bv) { bv = v0; bc = c0; }
                        float v1 = acc[i][j][half * 2 + 1];
                        if (v1 > bv) { bv = v1; bc = c0 + 1; }
                    }
#pragma unroll
                    for (int off = 1; off < 4; off <<= 1) {
                        float ov = __shfl_xor_sync(~0u, bv, off);
                        int   oc = __shfl_xor_sync(~0u, bc, off);
                        if (ov > bv || (ov == bv && oc < bc)) { bv = ov; bc = oc; }
                    }
                    if ((lane & 3) == 0) {
                        const int rloc = wm * 64 + i * 16 + half * 8 + (lane >> 2);
                        atomicMax(&table[rloc], packsc(bv, bc));
                    }
                }
            __syncthreads();
            // merge with global running row max -> cut
            if (tid < 128) {
                unsigned long long loc = table[tid];
                unsigned long long old = atomicMax(&g_gmax[qrow0 + tid], loc);
                if (old > loc) loc = old;
                tableF[tid] = unpack_score(loc) - MARGIN;
            }
            __syncthreads();
            // phase 2: append candidates >= cut
#pragma unroll
            for (int i = 0; i < 4; i++)
#pragma unroll
                for (int half = 0; half < 2; half++) {
                    const int rloc = wm * 64 + i * 16 + half * 8 + (lane >> 2);
                    const float cut = tableF[rloc];
                    const int rg = qrow0 + rloc;
#pragma unroll
                    for (int j = 0; j < 4; j++)
#pragma unroll
                        for (int c = 0; c < 2; c++) {
                            float v = acc[i][j][half * 2 + c];
                            if (v >= cut) {
                                int slot = atomicAdd(&g_cnt[rg], 1);
                                if (slot < CAP)
                                    g_cand[(size_t)rg * CAP + slot] = colbase + j * 8 + c;
                            }
                        }
                }
            __syncthreads();
            if (tid < 128) table[tid] = 0ull;
            // no extra sync needed: next table use is >=24 chunks away,
            // separated by per-chunk __syncthreads.
#pragma unroll
            for (int i = 0; i < 4; i++)
#pragma unroll
                for (int j = 0; j < 4; j++)
#pragma unroll
                    for (int c = 0; c < 4; c++) acc[i][j][c] = 0.f;
        }
    }
}

// ---------------------------------------------------------------------------
// Fused exact rescore + blend. One block (192 thr) per row.
// out layout: [reuse_map (B*N)] [reuse_input (B*N*D)] [reuse_value (B*N*D)]
// ---------------------------------------------------------------------------
__global__ __launch_bounds__(192) void rescore_blend_kernel(
    const float* __restrict__ Qi, const float* __restrict__ Qv,
    const float* __restrict__ Ci, const float* __restrict__ Cv,
    const float* __restrict__ thr_raw, float* __restrict__ out) {
    const int r = blockIdx.x;
    const int b = r >> 11;
    const int n = r & (NN - 1);
    const int t = threadIdx.x, wid = t >> 5, lane = t & 31;

    __shared__ __align__(16) float q[DD];
    __shared__ unsigned long long wbest[6];
    __shared__ float s_rm;
    __shared__ int s_idx;

    ((float4*)q)[t] = ((const float4*)(Qi + (size_t)r * DD))[t];
    __syncthreads();

    int cnt = g_cnt[r]; if (cnt > CAP) cnt = CAP;
    const float invq = g_invq[r];
    unsigned long long best = 0ull;
    for (int ci = wid; ci < cnt; ci += 6) {
        const int idx = g_cand[(size_t)r * CAP + ci];
        const float4* crow = (const float4*)(Ci + ((size_t)(b * NN + idx)) * DD);
        float s = 0.f;
#pragma unroll
        for (int u = 0; u < 6; u++) {
            float4 cv = crow[lane + 32 * u];
            float4 qv = ((const float4*)q)[lane + 32 * u];
            s += cv.x * qv.x + cv.y * qv.y + cv.z * qv.z + cv.w * qv.w;
        }
#pragma unroll
        for (int o = 16; o > 0; o >>= 1) s += __shfl_xor_sync(~0u, s, o);
        if (lane == 0) {
            unsigned long long p = packsc(s * invq * g_invc[b * NN + idx], idx);
            if (p > best) best = p;
        }
    }
    if (lane == 0) wbest[wid] = best;
    __syncthreads();
    if (t == 0) {
        unsigned long long B = 0ull;
#pragma unroll
        for (int w = 0; w < 6; w++) if (wbest[w] > B) B = wbest[w];
        const float score = unpack_score(B);
        const int idx = 2047 - (int)(uint32_t)(B & 0xFFFFFFFFull);
        const float thr = 1.f / (1.f + expf(-thr_raw[n]));
        const float rm  = 1.f / (1.f + expf(-40.f * (score - thr)));
        s_rm = rm; s_idx = idx;
        out[r] = rm;
    }
    __syncthreads();
    const float rm = s_rm, om = 1.f - rm;
    const int idx = s_idx;
    const float4* qv = (const float4*)(Qv + (size_t)r * DD);
    const float4* ci = (const float4*)(Ci + ((size_t)b * NN + idx) * DD);
    const float4* cv = (const float4*)(Cv + ((size_t)b * NN + idx) * DD);
    float4* oi = (float4*)(out + ROWS + (size_t)r * DD);
    float4* ov = (float4*)(out + ROWS + (size_t)ROWS * DD + (size_t)r * DD);

    float4 a = ((const float4*)q)[t], c = ci[t];
    oi[t] = make_float4(om * a.x + rm * c.x, om * a.y + rm * c.y,
                        om * a.z + rm * c.z, om * a.w + rm * c.w);
    float4 av = qv[t], cvv = cv[t];
    ov[t] = make_float4(om * av.x + rm * cvv.x, om * av.y + rm * cvv.y,
                        om * av.z + rm * cvv.z, om * av.w + rm * cvv.w);
}

// ---------------------------------------------------------------------------
extern "C" void kernel_launch(void* const* d_in, const int* in_sizes, int n_in,
                              void* d_out, int out_size) {
    const float* Qi = (const float*)d_in[0];
    const float* Qv = (const float*)d_in[1];
    const float* Ci = (const float*)d_in[2];
    const float* Cv = (const float*)d_in[3];
    const float* Th = (const float*)d_in[4];
    float* out = (float*)d_out;

    cudaFuncSetAttribute(gemm_kernel,
                         cudaFuncAttributeMaxDynamicSharedMemorySize, SMEM_DYN);

    prep_kernel<<<dim3(ROWS, 2), 192>>>(Qi, Ci);
    gemm_kernel<<<GRID, 256, SMEM_DYN>>>();
    rescore_blend_kernel<<<ROWS, 192>>>(Qi, Qv, Ci, Cv, Th, out);
}